// round 11
// baseline (speedup 1.0000x reference)
#include <cuda_runtime.h>
#include <cuda_fp16.h>
#include <cstdint>

// QKVAttentionLegacy, pure fp16 mma.sync, fp32 accum.
// R11 = R10's 4-CTA/SM desync structure + 32 query rows per warp:
// every K/V ldmatrix fragment feeds TWO 16-row MMAs (halves LDS bytes/query,
// which R10's profile shows as the binding pipe: L1 68%).
// 128-thr CTA = 4 warps x 32 rows = 128 q; tile processed in four s-quarters
// of 16 keys to keep transients small (reg cap 128 for 4 CTAs/SM).
// bs=2, heads=16 -> 32 bh, ch=64, T=2048, S=2560; 40 key tiles of 64.

#define NTHREADS 128
#define NS_TILES 40
#define TILE_BYTES 16384          // K(8KB) | V(8KB) fp16 swizzled images

#define SM_Q    0                  // Q tile: 128t x 64c fp16 = 16KB
#define SM_BUF0 16384
#define SM_BUF1 32768
#define SM_TOTAL 49152             // 48KB/CTA -> 4 CTAs/SM = 192KB

// scratch: [32 bh][40 tiles][16KB tile image]
__device__ __align__(16) char g_scratch[32u * NS_TILES * TILE_BYTES];

static __device__ __forceinline__ uint32_t swz(uint32_t r, uint32_t c) {
    // byte offset of element (row r, col c) in a [*][64] fp16 tile
    return (r << 7) + ((((c >> 3) ^ (r & 7)) & 7) << 4) + ((c & 7) << 1);
}
static __device__ __forceinline__ uint32_t smem_u32(const void* p) {
    uint32_t a;
    asm("{ .reg .u64 t; cvta.to.shared.u64 t, %1; cvt.u32.u64 %0, t; }" : "=r"(a) : "l"(p));
    return a;
}
static __device__ __forceinline__ float ex2(float x) {
    float y; asm("ex2.approx.f32 %0, %1;" : "=f"(y) : "f"(x));
    return y;
}

#define LDSM_X4(R0,R1,R2,R3,A) \
    asm volatile("ldmatrix.sync.aligned.m8n8.x4.shared.b16 {%0,%1,%2,%3}, [%4];" \
        : "=r"(R0),"=r"(R1),"=r"(R2),"=r"(R3) : "r"(A))
#define LDSM_X4T(R0,R1,R2,R3,A) \
    asm volatile("ldmatrix.sync.aligned.m8n8.x4.trans.shared.b16 {%0,%1,%2,%3}, [%4];" \
        : "=r"(R0),"=r"(R1),"=r"(R2),"=r"(R3) : "r"(A))
#define MMA16816(D, A0,A1,A2,A3, B0,B1) \
    asm volatile("mma.sync.aligned.m16n8k16.row.col.f32.f16.f16.f32 " \
        "{%0,%1,%2,%3}, {%4,%5,%6,%7}, {%8,%9}, {%0,%1,%2,%3};" \
        : "+f"((D)[0]),"+f"((D)[1]),"+f"((D)[2]),"+f"((D)[3]) \
        : "r"(A0),"r"(A1),"r"(A2),"r"(A3),"r"(B0),"r"(B1))

static __device__ __forceinline__ void cpa16(uint32_t dst, const void* src) {
    asm volatile("cp.async.cg.shared.global [%0], [%1], 16;" :: "r"(dst), "l"(src));
}
#define CP_COMMIT() asm volatile("cp.async.commit_group;" ::: "memory")
#define CP_WAIT(n)  asm volatile("cp.async.wait_group %0;" :: "n"(n) : "memory")

// ---- prologue: one 64x64 fp32 tile -> fp16 swizzled image ----
static __device__ __forceinline__ void conv_tile(
    const float* __restrict__ src, size_t stride, char* dst, int tid)
{
    const int c  = tid >> 2;
    const int s0 = (tid & 3) << 4;
    const float* p = src + (size_t)c * stride + s0;
    float4 f[4];
    f[0] = *(const float4*)(p);
    f[1] = *(const float4*)(p + 4);
    f[2] = *(const float4*)(p + 8);
    f[3] = *(const float4*)(p + 12);
    const float* v = (const float*)f;
    uint32_t h[8];
    #pragma unroll
    for (int i = 0; i < 8; ++i) {
        __half2 hh = __floats2half2_rn(v[2 * i], v[2 * i + 1]);
        h[i] = *(uint32_t*)&hh;
    }
    *(uint4*)(dst + swz(c, s0))     = make_uint4(h[0], h[1], h[2], h[3]);
    *(uint4*)(dst + swz(c, s0 + 8)) = make_uint4(h[4], h[5], h[6], h[7]);
}

__global__ __launch_bounds__(256) void conv_kv_kernel(
    const float* __restrict__ qkv, const float* __restrict__ ekv)
{
    const int st = blockIdx.x;   // 0..39
    const int bh = blockIdx.y;   // 0..31
    const int b = bh >> 4, h = bh & 15;
    const float* qbase  = qkv + ((size_t)b * 3072 + (size_t)h * 192) * 2048;
    const float* kbase  = qbase + (size_t)64  * 2048;
    const float* vbase  = qbase + (size_t)128 * 2048;
    const float* ekbase = ekv + ((size_t)b * 2048 + (size_t)h * 128) * 512;
    const float* evbase = ekbase + (size_t)64 * 512;

    const float* ksrc; const float* vsrc; size_t stride;
    if (st < 8) { ksrc = ekbase + st * 64; vsrc = evbase + st * 64; stride = 512; }
    else        { ksrc = kbase + (st - 8) * 64; vsrc = vbase + (st - 8) * 64; stride = 2048; }

    char* dst = g_scratch + ((size_t)bh * NS_TILES + st) * TILE_BYTES;
    conv_tile(ksrc, stride, dst,        threadIdx.x);
    conv_tile(vsrc, stride, dst + 8192, threadIdx.x);
}

__global__ __launch_bounds__(NTHREADS, 4) void qkv_attn_mma(
    const float* __restrict__ qkv,
    float* __restrict__ out)
{
    extern __shared__ char smb[];
    const uint32_t sb = smem_u32(smb);
    const int tid  = threadIdx.x;
    const int wid  = tid >> 5;          // 0..3
    const int lane = tid & 31;
    const int m0   = wid * 32;          // this warp's query rows [m0, m0+32)

    const int t_tile = blockIdx.x;      // 0..15 (128-query tiles)
    const int bh     = blockIdx.y;      // 0..31
    const int b = bh >> 4;
    const int h = bh & 15;
    const int t0 = t_tile * 128;

    const float* qbase = qkv + ((size_t)b * 3072 + (size_t)h * 192) * 2048;
    const char*  kv0   = g_scratch + (size_t)bh * NS_TILES * TILE_BYTES;

    // ---- start tile 0 load (16KB / 128 thr = 8 x 16B each) ----
    {
        const char* src = kv0 + tid * 16;
        uint32_t d = sb + SM_BUF0 + tid * 16;
        #pragma unroll
        for (int i = 0; i < 8; ++i) cpa16(d + i * 2048, src + i * 2048);
        CP_COMMIT();
    }

    // ---- stage Q [128t x 64c] fp16 (transpose + scale*log2e) ----
    #pragma unroll 1
    for (int ci = 0; ci < 16; ++ci) {
        int c = wid + 4 * ci;
        const float* qrow = qbase + (size_t)c * 2048 + t0;
        #pragma unroll
        for (int j = 0; j < 4; ++j) {
            int t = lane + 32 * j;
            float x = qrow[t] * (0.125f * 1.44269504f);
            *(__half*)(smb + SM_Q + swz(t, c)) = __float2half_rn(x);
        }
    }
    __syncthreads();

    // ---- Q A-fragments for both 16-row blocks, kept for all 40 tiles ----
    uint32_t qh[2][4][4];
    {
        int qcg = (lane >> 4) << 3;
        #pragma unroll
        for (int rb = 0; rb < 2; ++rb) {
            int qr = m0 + rb * 16 + (lane & 15);
            #pragma unroll
            for (int ks = 0; ks < 4; ++ks)
                LDSM_X4(qh[rb][ks][0], qh[rb][ks][1], qh[rb][ks][2], qh[rb][ks][3],
                        sb + SM_Q + swz(qr, ks * 16 + qcg));
        }
    }

    float o[2][8][4];
    #pragma unroll
    for (int rb = 0; rb < 2; ++rb)
        #pragma unroll
        for (int j = 0; j < 8; ++j)
            #pragma unroll
            for (int r = 0; r < 4; ++r) o[rb][j][r] = 0.0f;
    float lsum[2][2] = {{0.f, 0.f}, {0.f, 0.f}};

    const int krow = lane & 15;               // + ks*16
    const int kcol = (lane >> 4) << 3;        // + sq*16
    const int vrow = (lane & 7) + ((lane >> 4) << 3);   // + ng*16
    const int vcol = ((lane >> 3) & 1) << 3;            // + sq*16

    #pragma unroll 1
    for (int st = 0; st < NS_TILES; ++st) {
        // prefetch next tile into the other buffer, then wait for this tile
        if (st + 1 < NS_TILES) {
            const char* src = kv0 + (size_t)(st + 1) * TILE_BYTES + tid * 16;
            uint32_t d = sb + ((st + 1) & 1 ? SM_BUF1 : SM_BUF0) + tid * 16;
            #pragma unroll
            for (int i = 0; i < 8; ++i) cpa16(d + i * 2048, src + i * 2048);
            CP_COMMIT();
            CP_WAIT(1);
        } else {
            CP_WAIT(0);
        }
        __syncthreads();

        const uint32_t base = sb + (st & 1 ? SM_BUF1 : SM_BUF0);
        const uint32_t kh_b = base;              // K fp16 image [c][s]
        const uint32_t vh_b = base + 8192;       // V fp16 image [c][s]

        // four s-quarters of 16 keys; short phases, 2 rb chains for ILP
        #pragma unroll
        for (int sq = 0; sq < 4; ++sq) {
            // ---- GEMM1: d[rb][16 s-cols] = Q x K ----
            float d[2][2][4];
            #pragma unroll
            for (int rb = 0; rb < 2; ++rb)
                #pragma unroll
                for (int j = 0; j < 2; ++j)
                    #pragma unroll
                    for (int r = 0; r < 4; ++r) d[rb][j][r] = 0.0f;

            #pragma unroll
            for (int ks = 0; ks < 4; ++ks) {
                uint32_t b0, b1, b2, b3;
                LDSM_X4T(b0, b1, b2, b3, kh_b + swz(ks * 16 + krow, sq * 16 + kcol));
                #pragma unroll
                for (int rb = 0; rb < 2; ++rb) {
                    MMA16816(d[rb][0], qh[rb][ks][0], qh[rb][ks][1], qh[rb][ks][2], qh[rb][ks][3], b0, b1);
                    MMA16816(d[rb][1], qh[rb][ks][0], qh[rb][ks][1], qh[rb][ks][2], qh[rb][ks][3], b2, b3);
                }
            }

            // ---- softmax p = 2^score; pack P A-fragment for k-step sq ----
            uint32_t pa[2][4];
            #pragma unroll
            for (int rb = 0; rb < 2; ++rb) {
                #pragma unroll
                for (int j = 0; j < 2; ++j) {
                    float p0 = ex2(d[rb][j][0]);
                    float p1 = ex2(d[rb][j][1]);
                    float p2 = ex2(d[rb][j][2]);
                    float p3 = ex2(d[rb][j][3]);
                    lsum[rb][0] += p0 + p1;
                    lsum[rb][1] += p2 + p3;
                    __half2 h01 = __floats2half2_rn(p0, p1);
                    __half2 h23 = __floats2half2_rn(p2, p3);
                    pa[rb][2 * j]     = *(uint32_t*)&h01;
                    pa[rb][2 * j + 1] = *(uint32_t*)&h23;
                }
            }

            // ---- GEMM2: O += P x V for this 16-key k-step ----
            #pragma unroll
            for (int ng = 0; ng < 4; ++ng) {
                uint32_t b0, b1, b2, b3;
                LDSM_X4(b0, b1, b2, b3, vh_b + swz(ng * 16 + vrow, sq * 16 + vcol));
                #pragma unroll
                for (int rb = 0; rb < 2; ++rb) {
                    MMA16816(o[rb][2 * ng],     pa[rb][0], pa[rb][1], pa[rb][2], pa[rb][3], b0, b1);
                    MMA16816(o[rb][2 * ng + 1], pa[rb][0], pa[rb][1], pa[rb][2], pa[rb][3], b2, b3);
                }
            }
        }
        __syncthreads();   // all warps done with this buffer before refill
    }

    // ---- epilogue ----
    #pragma unroll
    for (int rb = 0; rb < 2; ++rb) {
        float l0 = lsum[rb][0], l1 = lsum[rb][1];
        l0 += __shfl_xor_sync(0xffffffffu, l0, 1);
        l0 += __shfl_xor_sync(0xffffffffu, l0, 2);
        l1 += __shfl_xor_sync(0xffffffffu, l1, 1);
        l1 += __shfl_xor_sync(0xffffffffu, l1, 2);
        float rl0 = 1.0f / l0;
        float rl1 = 1.0f / l1;

        const int tg = t0 + m0 + rb * 16 + (lane >> 2);
        #pragma unroll
        for (int j = 0; j < 8; ++j) {
            int c = j * 8 + (lane & 3) * 2;
            float* p = out + ((size_t)(b * 1024 + h * 64 + c)) * 2048 + tg;
            p[0]        = o[rb][j][0] * rl0;
            p[2048]     = o[rb][j][1] * rl0;
            p[8]        = o[rb][j][2] * rl1;
            p[2048 + 8] = o[rb][j][3] * rl1;
        }
    }
}

extern "C" void kernel_launch(void* const* d_in, const int* in_sizes, int n_in,
                              void* d_out, int out_size)
{
    const float* qkv;
    const float* ekv;
    if (in_sizes[0] == 2 * 3072 * 2048) {
        qkv = (const float*)d_in[0];
        ekv = (const float*)d_in[1];
    } else {
        qkv = (const float*)d_in[1];
        ekv = (const float*)d_in[0];
    }
    float* out = (float*)d_out;

    // prologue: pre-convert K/V to fp16 swizzled tile images
    dim3 cgrid(NS_TILES, 32);
    conv_kv_kernel<<<cgrid, 256>>>(qkv, ekv);

    cudaFuncSetAttribute(qkv_attn_mma,
                         cudaFuncAttributeMaxDynamicSharedMemorySize, SM_TOTAL);
    dim3 grid(16, 32);   // (t-tiles of 128, batch-heads)
    qkv_attn_mma<<<grid, NTHREADS, SM_TOTAL>>>(qkv, out);
}

// round 12
// speedup vs baseline: 1.2532x; 1.2532x over previous
#include <cuda_runtime.h>
#include <cuda_fp16.h>
#include <cstdint>

// QKVAttentionLegacy, pure fp16 mma.sync, fp32 accum.
// R12 = R10 (4 warps x 16 q-rows, 128 thr, 4 CTAs/SM desync) + TRIPLE
// buffering: slot(st+1)%3 != slot(st-1)%3 removes the end-of-loop barrier.
// One __syncthreads per tile; warps may skew +-1 tile -> intra-CTA phase
// mixing on top of R10's inter-CTA desync.
// bs=2, heads=16 -> 32 bh, ch=64, T=2048, S=2560; 40 key tiles of 64.

#define NTHREADS 128
#define NS_TILES 40
#define TILE_BYTES 16384          // K(8KB) | V(8KB) fp16 swizzled images

#define SM_Q    0                  // Q tile: 64t x 64c fp16 = 8KB
#define SM_BUF0 8192               // 3 x 16KB ring
#define SM_TOTAL (8192 + 3 * TILE_BYTES)   // 57344 B; x4 CTAs = 229376 <= 233472

// scratch: [32 bh][40 tiles][16KB tile image]
__device__ __align__(16) char g_scratch[32u * NS_TILES * TILE_BYTES];

static __device__ __forceinline__ uint32_t swz(uint32_t r, uint32_t c) {
    // byte offset of element (row r, col c) in a [*][64] fp16 tile
    return (r << 7) + ((((c >> 3) ^ (r & 7)) & 7) << 4) + ((c & 7) << 1);
}
static __device__ __forceinline__ uint32_t smem_u32(const void* p) {
    uint32_t a;
    asm("{ .reg .u64 t; cvta.to.shared.u64 t, %1; cvt.u32.u64 %0, t; }" : "=r"(a) : "l"(p));
    return a;
}
static __device__ __forceinline__ float ex2(float x) {
    float y; asm("ex2.approx.f32 %0, %1;" : "=f"(y) : "f"(x));
    return y;
}

#define LDSM_X4(R0,R1,R2,R3,A) \
    asm volatile("ldmatrix.sync.aligned.m8n8.x4.shared.b16 {%0,%1,%2,%3}, [%4];" \
        : "=r"(R0),"=r"(R1),"=r"(R2),"=r"(R3) : "r"(A))
#define LDSM_X4T(R0,R1,R2,R3,A) \
    asm volatile("ldmatrix.sync.aligned.m8n8.x4.trans.shared.b16 {%0,%1,%2,%3}, [%4];" \
        : "=r"(R0),"=r"(R1),"=r"(R2),"=r"(R3) : "r"(A))
#define MMA16816(D, A0,A1,A2,A3, B0,B1) \
    asm volatile("mma.sync.aligned.m16n8k16.row.col.f32.f16.f16.f32 " \
        "{%0,%1,%2,%3}, {%4,%5,%6,%7}, {%8,%9}, {%0,%1,%2,%3};" \
        : "+f"((D)[0]),"+f"((D)[1]),"+f"((D)[2]),"+f"((D)[3]) \
        : "r"(A0),"r"(A1),"r"(A2),"r"(A3),"r"(B0),"r"(B1))

static __device__ __forceinline__ void cpa16(uint32_t dst, const void* src) {
    asm volatile("cp.async.cg.shared.global [%0], [%1], 16;" :: "r"(dst), "l"(src));
}
#define CP_COMMIT() asm volatile("cp.async.commit_group;" ::: "memory")
#define CP_WAIT(n)  asm volatile("cp.async.wait_group %0;" :: "n"(n) : "memory")

// ---- prologue: one 64x64 fp32 tile -> fp16 swizzled image ----
static __device__ __forceinline__ void conv_tile(
    const float* __restrict__ src, size_t stride, char* dst, int tid)
{
    const int c  = tid >> 2;
    const int s0 = (tid & 3) << 4;
    const float* p = src + (size_t)c * stride + s0;
    float4 f[4];
    f[0] = *(const float4*)(p);
    f[1] = *(const float4*)(p + 4);
    f[2] = *(const float4*)(p + 8);
    f[3] = *(const float4*)(p + 12);
    const float* v = (const float*)f;
    uint32_t h[8];
    #pragma unroll
    for (int i = 0; i < 8; ++i) {
        __half2 hh = __floats2half2_rn(v[2 * i], v[2 * i + 1]);
        h[i] = *(uint32_t*)&hh;
    }
    *(uint4*)(dst + swz(c, s0))     = make_uint4(h[0], h[1], h[2], h[3]);
    *(uint4*)(dst + swz(c, s0 + 8)) = make_uint4(h[4], h[5], h[6], h[7]);
}

__global__ __launch_bounds__(256) void conv_kv_kernel(
    const float* __restrict__ qkv, const float* __restrict__ ekv)
{
    const int st = blockIdx.x;   // 0..39
    const int bh = blockIdx.y;   // 0..31
    const int b = bh >> 4, h = bh & 15;
    const float* qbase  = qkv + ((size_t)b * 3072 + (size_t)h * 192) * 2048;
    const float* kbase  = qbase + (size_t)64  * 2048;
    const float* vbase  = qbase + (size_t)128 * 2048;
    const float* ekbase = ekv + ((size_t)b * 2048 + (size_t)h * 128) * 512;
    const float* evbase = ekbase + (size_t)64 * 512;

    const float* ksrc; const float* vsrc; size_t stride;
    if (st < 8) { ksrc = ekbase + st * 64; vsrc = evbase + st * 64; stride = 512; }
    else        { ksrc = kbase + (st - 8) * 64; vsrc = vbase + (st - 8) * 64; stride = 2048; }

    char* dst = g_scratch + ((size_t)bh * NS_TILES + st) * TILE_BYTES;
    conv_tile(ksrc, stride, dst,        threadIdx.x);
    conv_tile(vsrc, stride, dst + 8192, threadIdx.x);
}

__global__ __launch_bounds__(NTHREADS, 4) void qkv_attn_mma(
    const float* __restrict__ qkv,
    float* __restrict__ out)
{
    extern __shared__ char smb[];
    const uint32_t sb = smem_u32(smb);
    const int tid  = threadIdx.x;
    const int wid  = tid >> 5;          // 0..3
    const int lane = tid & 31;
    const int m0   = wid * 16;          // this warp's query rows [m0, m0+16)

    const int t_tile = blockIdx.x;      // 0..31 (64-query tiles)
    const int bh     = blockIdx.y;      // 0..31
    const int b = bh >> 4;
    const int h = bh & 15;
    const int t0 = t_tile * 64;

    const float* qbase = qkv + ((size_t)b * 3072 + (size_t)h * 192) * 2048;
    const char*  kv0   = g_scratch + (size_t)bh * NS_TILES * TILE_BYTES;

    // ---- start tile 0 load (16KB / 128 thr = 8 x 16B each) ----
    {
        const char* src = kv0 + tid * 16;
        uint32_t d = sb + SM_BUF0 + tid * 16;
        #pragma unroll
        for (int i = 0; i < 8; ++i) cpa16(d + i * 2048, src + i * 2048);
        CP_COMMIT();
    }

    // ---- stage Q [64t x 64c] fp16 (transpose + scale*log2e) ----
    #pragma unroll 1
    for (int ci = 0; ci < 16; ++ci) {
        int c = wid + 4 * ci;
        const float* qrow = qbase + (size_t)c * 2048 + t0;
        #pragma unroll
        for (int j = 0; j < 2; ++j) {
            int t = lane + 32 * j;
            float x = qrow[t] * (0.125f * 1.44269504f);
            *(__half*)(smb + SM_Q + swz(t, c)) = __float2half_rn(x);
        }
    }
    __syncthreads();

    // ---- Q A-fragments, kept in regs for all 40 tiles ----
    uint32_t qh[4][4];
    {
        int qr  = m0 + (lane & 15);
        int qcg = (lane >> 4) << 3;
        #pragma unroll
        for (int ks = 0; ks < 4; ++ks)
            LDSM_X4(qh[ks][0], qh[ks][1], qh[ks][2], qh[ks][3],
                    sb + SM_Q + swz(qr, ks * 16 + qcg));
    }

    float o[8][4];
    #pragma unroll
    for (int j = 0; j < 8; ++j)
        #pragma unroll
        for (int r = 0; r < 4; ++r) o[j][r] = 0.0f;
    float l0 = 0.0f, l1 = 0.0f;

    const int krow = lane & 15;               // + ks*16
    const int kcol = (lane >> 4) << 3;        // + ng*16
    const int vrow = (lane & 7) + ((lane >> 4) << 3);   // + ng*16
    const int vcol = ((lane >> 3) & 1) << 3;            // + ks*16

    // ring slot bases: cur = st%3, nxt = (st+1)%3
    uint32_t cur_b = sb + SM_BUF0;
    uint32_t nxt_b = sb + SM_BUF0 + TILE_BYTES;

    #pragma unroll 1
    for (int st = 0; st < NS_TILES; ++st) {
        // prefetch next tile into ring slot (st+1)%3, wait for this tile
        if (st + 1 < NS_TILES) {
            const char* src = kv0 + (size_t)(st + 1) * TILE_BYTES + tid * 16;
            uint32_t d = nxt_b + tid * 16;
            #pragma unroll
            for (int i = 0; i < 8; ++i) cpa16(d + i * 2048, src + i * 2048);
            CP_COMMIT();
            CP_WAIT(1);
        } else {
            CP_WAIT(0);
        }
        __syncthreads();   // ONLY barrier per tile: slot (st+1)%3 never
                           // collides with a laggard reading slot (st-1)%3

        const uint32_t kh_b = cur_b;             // K fp16 image [c][s]
        const uint32_t vh_b = cur_b + 8192;      // V fp16 image [c][s]

        // advance ring
        cur_b = nxt_b;
        nxt_b = nxt_b + TILE_BYTES;
        if (nxt_b == sb + SM_BUF0 + 3 * TILE_BYTES) nxt_b = sb + SM_BUF0;

        // ---- GEMM1: D[16t x 64s] = Q x K (1-pass fp16) ----
        float d[8][4];
        #pragma unroll
        for (int j = 0; j < 8; ++j)
            #pragma unroll
            for (int r = 0; r < 4; ++r) d[j][r] = 0.0f;

        #pragma unroll
        for (int ks = 0; ks < 4; ++ks) {
            #pragma unroll
            for (int ng = 0; ng < 4; ++ng) {
                uint32_t b0, b1, b2, b3;
                LDSM_X4T(b0, b1, b2, b3, kh_b + swz(ks * 16 + krow, ng * 16 + kcol));
                MMA16816(d[2 * ng],     qh[ks][0], qh[ks][1], qh[ks][2], qh[ks][3], b0, b1);
                MMA16816(d[2 * ng + 1], qh[ks][0], qh[ks][1], qh[ks][2], qh[ks][3], b2, b3);
            }
        }

        // ---- softmax p = 2^score (log2e folded into Q); pack P fragments ----
        uint32_t pa[4][4];
        #pragma unroll
        for (int j = 0; j < 8; ++j) {
            float p0 = ex2(d[j][0]);
            float p1 = ex2(d[j][1]);
            float p2 = ex2(d[j][2]);
            float p3 = ex2(d[j][3]);
            l0 += p0 + p1;
            l1 += p2 + p3;
            __half2 h01 = __floats2half2_rn(p0, p1);
            __half2 h23 = __floats2half2_rn(p2, p3);
            int ks = j >> 1, q = (j & 1) * 2;
            pa[ks][q]     = *(uint32_t*)&h01;
            pa[ks][q + 1] = *(uint32_t*)&h23;
        }

        // ---- GEMM2: O[16t x 64c] += P x V (1-pass fp16) ----
        #pragma unroll
        for (int ks = 0; ks < 4; ++ks) {
            #pragma unroll
            for (int ng = 0; ng < 4; ++ng) {
                uint32_t b0, b1, b2, b3;
                LDSM_X4(b0, b1, b2, b3, vh_b + swz(ng * 16 + vrow, ks * 16 + vcol));
                MMA16816(o[2 * ng],     pa[ks][0], pa[ks][1], pa[ks][2], pa[ks][3], b0, b1);
                MMA16816(o[2 * ng + 1], pa[ks][0], pa[ks][1], pa[ks][2], pa[ks][3], b2, b3);
            }
        }
        // no trailing barrier: triple buffer guarantees no write/read overlap
    }

    // ---- epilogue: row sums across the 4 lanes sharing a row, then STG ----
    l0 += __shfl_xor_sync(0xffffffffu, l0, 1);
    l0 += __shfl_xor_sync(0xffffffffu, l0, 2);
    l1 += __shfl_xor_sync(0xffffffffu, l1, 1);
    l1 += __shfl_xor_sync(0xffffffffu, l1, 2);
    float rl0 = 1.0f / l0;
    float rl1 = 1.0f / l1;

    const int tg = t0 + m0 + (lane >> 2);      // global t of this row
    #pragma unroll
    for (int j = 0; j < 8; ++j) {
        int c = j * 8 + (lane & 3) * 2;
        float* p = out + ((size_t)(b * 1024 + h * 64 + c)) * 2048 + tg;
        p[0]        = o[j][0] * rl0;
        p[2048]     = o[j][1] * rl0;
        p[8]        = o[j][2] * rl1;
        p[2048 + 8] = o[j][3] * rl1;
    }
}

extern "C" void kernel_launch(void* const* d_in, const int* in_sizes, int n_in,
                              void* d_out, int out_size)
{
    const float* qkv;
    const float* ekv;
    if (in_sizes[0] == 2 * 3072 * 2048) {
        qkv = (const float*)d_in[0];
        ekv = (const float*)d_in[1];
    } else {
        qkv = (const float*)d_in[1];
        ekv = (const float*)d_in[0];
    }
    float* out = (float*)d_out;

    // prologue: pre-convert K/V to fp16 swizzled tile images
    dim3 cgrid(NS_TILES, 32);
    conv_kv_kernel<<<cgrid, 256>>>(qkv, ekv);

    cudaFuncSetAttribute(qkv_attn_mma,
                         cudaFuncAttributeMaxDynamicSharedMemorySize, SM_TOTAL);
    dim3 grid(32, 32);   // (t-tiles of 64, batch-heads)
    qkv_attn_mma<<<grid, NTHREADS, SM_TOTAL>>>(qkv, out);
}